// round 6
// baseline (speedup 1.0000x reference)
#include <cuda_runtime.h>
#include <cuda_fp16.h>

#define N_NODES 50000
#define N_EDGES 800000
#define IN_DIM  100
#define OUT_DIM 40
#define CH      25           // float4 chunks per fp32 row (100/4)
#define CH4     13           // uint4 chunks per fp16 row (8 feats each, 104 padded)
#define SCAN_B  256
#define NSB     196          // ceil(50000/256)
#define NPB     19           // nodes per spmm block (19*13=247 of 256 threads)
#define NPART   128          // stats partial buffers

// ---------------- scratch (device globals) ----------------------------------
__device__ float4 g_B0[N_NODES * CH];          // final H (fp32)
__device__ uint4  g_P[N_NODES * CH4];          // fp16 ping (104-feat padded rows)
__device__ uint4  g_Q[N_NODES * CH4];          // fp16 pong
__device__ float  g_norm[N_NODES];
__device__ int    g_deg[N_NODES];
__device__ int    g_rowptr[N_NODES + 1];
__device__ int    g_pos[N_NODES];
__device__ int    g_bsum[NSB];
__device__ int    g_esrc[N_EDGES];
__device__ float  g_psum[NPART][IN_DIM];
__device__ float  g_psq[NPART][IN_DIM];

// ---------------- degree histogram (g_deg zeroed by prev run / load) ---------
__global__ void k_degree(const int* __restrict__ dst) {
    int i = blockIdx.x * blockDim.x + threadIdx.x;
    if (i < N_EDGES) atomicAdd(&g_deg[dst[i]], 1);
}

// ---- warp-shuffle scan chain ----
__global__ void k_scan1() {
    int t = threadIdx.x;
    int i = blockIdx.x * SCAN_B + t;
    int v = (i < N_NODES) ? g_deg[i] : 0;
    int lane = t & 31, w = t >> 5;
    int x = v;
    #pragma unroll
    for (int off = 1; off < 32; off <<= 1) {
        int y = __shfl_up_sync(0xffffffffu, x, off);
        if (lane >= off) x += y;
    }
    __shared__ int wsum[8];
    if (lane == 31) wsum[w] = x;
    __syncthreads();
    if (w == 0) {
        int s = (lane < 8) ? wsum[lane] : 0;
        #pragma unroll
        for (int off = 1; off < 8; off <<= 1) {
            int y = __shfl_up_sync(0xffffffffu, s, off);
            if (lane >= off) s += y;
        }
        if (lane < 8) wsum[lane] = s;
    }
    __syncthreads();
    int incl = x + (w > 0 ? wsum[w - 1] : 0);
    if (i < N_NODES) g_rowptr[i + 1] = incl;
    if (t == SCAN_B - 1) g_bsum[blockIdx.x] = incl;
    if (i == 0) g_rowptr[0] = 0;
}

__global__ void k_scan2() {
    int t = threadIdx.x;
    int v = (t < NSB) ? g_bsum[t] : 0;
    int lane = t & 31, w = t >> 5;
    int x = v;
    #pragma unroll
    for (int off = 1; off < 32; off <<= 1) {
        int y = __shfl_up_sync(0xffffffffu, x, off);
        if (lane >= off) x += y;
    }
    __shared__ int wsum[8];
    if (lane == 31) wsum[w] = x;
    __syncthreads();
    if (w == 0) {
        int s = (lane < 8) ? wsum[lane] : 0;
        #pragma unroll
        for (int off = 1; off < 8; off <<= 1) {
            int y = __shfl_up_sync(0xffffffffu, s, off);
            if (lane >= off) s += y;
        }
        if (lane < 8) wsum[lane] = s;
    }
    __syncthreads();
    int incl = x + (w > 0 ? wsum[w - 1] : 0);
    if (t < NSB) g_bsum[t] = incl - v;   // exclusive
}

// finalize rowptr + pos + norm + reset deg for next replay
__global__ void k_scan3np() {
    int i = blockIdx.x * SCAN_B + threadIdx.x;
    if (i >= N_NODES) return;
    int incl = g_rowptr[i + 1] + g_bsum[blockIdx.x];
    g_rowptr[i + 1] = incl;
    int d = g_deg[i];
    g_pos[i] = incl - d;
    g_norm[i] = rsqrtf(fmaxf((float)d, 1.0f));
    g_deg[i] = 0;
}

// ---------------- fused fill + fp16 pre-scale (uint4 rows) -------------------
#define NEB ((N_EDGES + 255) / 256)
__global__ void k_fill_pre(const int* __restrict__ src, const int* __restrict__ dst,
                           const float4* __restrict__ feat) {
    int b = blockIdx.x;
    if (b < NEB) {
        int i = b * 256 + threadIdx.x;
        if (i < N_EDGES) {
            int slot = atomicAdd(&g_pos[dst[i]], 1);
            g_esrc[slot] = src[i];
        }
    } else {
        int i = (b - NEB) * 256 + threadIdx.x;
        if (i < N_NODES * CH4) {
            int row = i / CH4;
            int c = i - row * CH4;
            float n = __ldg(&g_norm[row]);
            float4 f0 = __ldg(&feat[row * CH + 2 * c]);
            float4 f1 = (c < 12) ? __ldg(&feat[row * CH + 2 * c + 1])
                                 : make_float4(0.f, 0.f, 0.f, 0.f);
            half2 h0 = __floats2half2_rn(f0.x * n, f0.y * n);
            half2 h1 = __floats2half2_rn(f0.z * n, f0.w * n);
            half2 h2 = __floats2half2_rn(f1.x * n, f1.y * n);
            half2 h3 = __floats2half2_rn(f1.z * n, f1.w * n);
            uint4 o;
            o.x = *(unsigned*)&h0; o.y = *(unsigned*)&h1;
            o.z = *(unsigned*)&h2; o.w = *(unsigned*)&h3;
            g_P[i] = o;
        }
    }
}

// ---------------- pull SpMM (uint4 fp16 gather, fp32 accumulate) -------------
// MODE 1: P -> Q (block 0 zeroes stats partials)
// MODE 2: Q -> P
// MODE 3: P -> g_B0 fp32 + fused column stats
template <int MODE>
__global__ void __launch_bounds__(256) k_spmm16() {
    const uint4* __restrict__ in = (MODE == 2) ? g_Q : g_P;

    if (MODE == 1 && blockIdx.x == 0) {
        for (int i = threadIdx.x; i < NPART * IN_DIM; i += blockDim.x) {
            ((float*)g_psum)[i] = 0.f;
            ((float*)g_psq)[i] = 0.f;
        }
    }

    int t = threadIdx.x;
    int local = t / CH4;
    int c = t - local * CH4;
    int node = blockIdx.x * NPB + local;
    bool active = (t < NPB * CH4) && (node < N_NODES);

    float a0 = 0.f, a1 = 0.f, a2 = 0.f, a3 = 0.f;
    float a4 = 0.f, a5 = 0.f, a6 = 0.f, a7 = 0.f;
    float n = 0.f;
    if (active) {
        int beg = __ldg(&g_rowptr[node]);
        int end = __ldg(&g_rowptr[node + 1]);
        int e = beg;
        for (; e + 1 < end; e += 2) {
            int s0 = __ldg(&g_esrc[e]);
            int s1 = __ldg(&g_esrc[e + 1]);
            uint4 r0 = __ldg(&in[s0 * CH4 + c]);
            uint4 r1 = __ldg(&in[s1 * CH4 + c]);
            float2 p0 = __half22float2(*(half2*)&r0.x), q0 = __half22float2(*(half2*)&r1.x);
            float2 p1 = __half22float2(*(half2*)&r0.y), q1 = __half22float2(*(half2*)&r1.y);
            float2 p2 = __half22float2(*(half2*)&r0.z), q2 = __half22float2(*(half2*)&r1.z);
            float2 p3 = __half22float2(*(half2*)&r0.w), q3 = __half22float2(*(half2*)&r1.w);
            a0 += p0.x + q0.x; a1 += p0.y + q0.y;
            a2 += p1.x + q1.x; a3 += p1.y + q1.y;
            a4 += p2.x + q2.x; a5 += p2.y + q2.y;
            a6 += p3.x + q3.x; a7 += p3.y + q3.y;
        }
        if (e < end) {
            int s = __ldg(&g_esrc[e]);
            uint4 r = __ldg(&in[s * CH4 + c]);
            float2 p0 = __half22float2(*(half2*)&r.x);
            float2 p1 = __half22float2(*(half2*)&r.y);
            float2 p2 = __half22float2(*(half2*)&r.z);
            float2 p3 = __half22float2(*(half2*)&r.w);
            a0 += p0.x; a1 += p0.y; a2 += p1.x; a3 += p1.y;
            a4 += p2.x; a5 += p2.y; a6 += p3.x; a7 += p3.y;
        }
        n = __ldg(&g_norm[node]);
    }

    if (MODE == 3) {
        a0 *= n; a1 *= n; a2 *= n; a3 *= n;
        a4 *= n; a5 *= n; a6 *= n; a7 *= n;
        if (active) {
            g_B0[node * CH + 2 * c] = make_float4(a0, a1, a2, a3);
            if (c < 12)
                g_B0[node * CH + 2 * c + 1] = make_float4(a4, a5, a6, a7);
        }
        __shared__ float ssum[CH4][8];
        __shared__ float ssq[CH4][8];
        if (t < CH4 * 8) ((float*)ssum)[t] = 0.f;
        if (t < CH4 * 8) ((float*)ssq)[t] = 0.f;
        __syncthreads();
        if (active) {
            atomicAdd(&ssum[c][0], a0); atomicAdd(&ssum[c][1], a1);
            atomicAdd(&ssum[c][2], a2); atomicAdd(&ssum[c][3], a3);
            atomicAdd(&ssum[c][4], a4); atomicAdd(&ssum[c][5], a5);
            atomicAdd(&ssum[c][6], a6); atomicAdd(&ssum[c][7], a7);
            atomicAdd(&ssq[c][0], a0 * a0); atomicAdd(&ssq[c][1], a1 * a1);
            atomicAdd(&ssq[c][2], a2 * a2); atomicAdd(&ssq[c][3], a3 * a3);
            atomicAdd(&ssq[c][4], a4 * a4); atomicAdd(&ssq[c][5], a5 * a5);
            atomicAdd(&ssq[c][6], a6 * a6); atomicAdd(&ssq[c][7], a7 * a7);
        }
        __syncthreads();
        if (t < CH4) {
            int part = blockIdx.x & (NPART - 1);
            #pragma unroll
            for (int k = 0; k < 8; k++) {
                int f = t * 8 + k;
                if (f < IN_DIM) {
                    atomicAdd(&g_psum[part][f], ssum[t][k]);
                    atomicAdd(&g_psq[part][f], ssq[t][k]);
                }
            }
        }
    } else {
        if (active) {
            float f = n * n;
            half2 h0 = __floats2half2_rn(a0 * f, a1 * f);
            half2 h1 = __floats2half2_rn(a2 * f, a3 * f);
            half2 h2 = __floats2half2_rn(a4 * f, a5 * f);
            half2 h3 = __floats2half2_rn(a6 * f, a7 * f);
            uint4 o;
            o.x = *(unsigned*)&h0; o.y = *(unsigned*)&h1;
            o.z = *(unsigned*)&h2; o.w = *(unsigned*)&h3;
            ((MODE == 1) ? g_Q : g_P)[node * CH4 + c] = o;
        }
    }
}

// ---------------- fused partial-reduce + fold + GEMM -------------------------
__global__ void k_gemm_fold(const float* __restrict__ W, const float* __restrict__ b,
                            float* __restrict__ out) {
    __shared__ float s_mean[IN_DIM];
    __shared__ float s_istd[IN_DIM];
    __shared__ __align__(16) float s_Wt[IN_DIM * OUT_DIM];
    __shared__ float s_bn[OUT_DIM];
    int t = threadIdx.x;

    if (t < IN_DIM) {
        float s = 0.f, q = 0.f;
        #pragma unroll 8
        for (int p = 0; p < NPART; p++) {
            s += g_psum[p][t];
            q += g_psq[p][t];
        }
        float mean = s / (float)N_NODES;
        float var = (q - (float)N_NODES * mean * mean) / (float)(N_NODES - 1);
        s_mean[t] = mean;
        s_istd[t] = rsqrtf(var);
    }
    __syncthreads();
    for (int i = t; i < IN_DIM * OUT_DIM; i += blockDim.x) {
        int o = i / IN_DIM;
        int f = i - o * IN_DIM;
        s_Wt[f * OUT_DIM + o] = __ldg(&W[i]) * s_istd[f];
    }
    if (t < OUT_DIM) {
        float acc = __ldg(&b[t]);
        for (int f = 0; f < IN_DIM; f++)
            acc -= s_mean[f] * s_istd[f] * __ldg(&W[t * IN_DIM + f]);
        s_bn[t] = acc;
    }
    __syncthreads();

    int row = blockIdx.x * blockDim.x + t;
    if (row >= N_NODES) return;

    float acc[OUT_DIM];
    #pragma unroll
    for (int o = 0; o < OUT_DIM; o++) acc[o] = s_bn[o];

    #pragma unroll
    for (int c = 0; c < CH; c++) {
        float4 h4 = g_B0[row * CH + c];
        #pragma unroll
        for (int k = 0; k < 4; k++) {
            float hv = (k == 0) ? h4.x : (k == 1) ? h4.y : (k == 2) ? h4.z : h4.w;
            const float4* wr = (const float4*)&s_Wt[(c * 4 + k) * OUT_DIM];
            #pragma unroll
            for (int j = 0; j < 10; j++) {
                float4 w = wr[j];
                acc[4 * j + 0] += hv * w.x;
                acc[4 * j + 1] += hv * w.y;
                acc[4 * j + 2] += hv * w.z;
                acc[4 * j + 3] += hv * w.w;
            }
        }
    }
    float4* op = (float4*)(out + (size_t)row * OUT_DIM);
    #pragma unroll
    for (int j = 0; j < 10; j++)
        op[j] = make_float4(acc[4 * j + 0], acc[4 * j + 1], acc[4 * j + 2], acc[4 * j + 3]);
}

// ---------------- launch ------------------------------------------------------

extern "C" void kernel_launch(void* const* d_in, const int* in_sizes, int n_in,
                              void* d_out, int out_size) {
    const float4* feat = (const float4*)d_in[0];   // [N, 100] f32
    const float*  W    = (const float*)d_in[1];    // [40, 100] f32
    const float*  b    = (const float*)d_in[2];    // [40] f32
    const int*    src  = (const int*)d_in[3];      // [E] i32
    const int*    dst  = (const int*)d_in[4];      // [E] i32
    float*        out  = (float*)d_out;            // [N, 40] f32

    const int TB = 256;
    const int n_node_blk  = (N_NODES + TB - 1) / TB;
    const int n_edge_blk  = (N_EDGES + TB - 1) / TB;
    const int n_chunk_blk = (N_NODES * CH4 + TB - 1) / TB;
    const int n_spmm_blk  = (N_NODES + NPB - 1) / NPB;

    k_degree<<<n_edge_blk, TB>>>(dst);
    k_scan1<<<NSB, SCAN_B>>>();
    k_scan2<<<1, SCAN_B>>>();
    k_scan3np<<<NSB, SCAN_B>>>();
    k_fill_pre<<<n_edge_blk + n_chunk_blk, TB>>>(src, dst, feat);

    k_spmm16<1><<<n_spmm_blk, TB>>>();   // P -> Q (+zero partials)
    k_spmm16<2><<<n_spmm_blk, TB>>>();   // Q -> P
    k_spmm16<3><<<n_spmm_blk, TB>>>();   // P -> B0 (+stats)

    k_gemm_fold<<<n_node_blk, TB>>>(W, b, out);
}

// round 7
// speedup vs baseline: 1.2032x; 1.2032x over previous
#include <cuda_runtime.h>
#include <cuda_fp16.h>

#define N_NODES 50000
#define N_EDGES 800000
#define IN_DIM  100
#define OUT_DIM 40
#define CH      25           // 4-feature chunks per row (100/4)
#define SCAN_B  256
#define NSB     196          // ceil(50000/256)
#define NODES_PER_BLK 10     // 250 active threads of 256

// ---------------- scratch (device globals) ----------------------------------
__device__ float4 g_B0[N_NODES * CH];          // final H (fp32)
__device__ uint2  g_P[N_NODES * CH];           // fp16 ping
__device__ uint2  g_Q[N_NODES * CH];           // fp16 pong
__device__ float  g_norm[N_NODES];
__device__ int    g_deg[N_NODES];
__device__ int    g_rowptr[N_NODES + 1];
__device__ int    g_pos[N_NODES];
__device__ int    g_bsum[NSB];
__device__ int    g_esrc[N_EDGES];
__device__ float  g_colsum[IN_DIM];
__device__ float  g_colsq[IN_DIM];

// ---------------- degree histogram (g_deg zeroed by prev run / BSS init) -----
__global__ void k_degree(const int* __restrict__ dst) {
    int i = blockIdx.x * blockDim.x + threadIdx.x;
    if (i < N_EDGES) atomicAdd(&g_deg[dst[i]], 1);
}

// ---- warp-shuffle scan chain ----
__global__ void k_scan1() {
    int t = threadIdx.x;
    int i = blockIdx.x * SCAN_B + t;
    int v = (i < N_NODES) ? g_deg[i] : 0;
    int lane = t & 31, w = t >> 5;
    int x = v;
    #pragma unroll
    for (int off = 1; off < 32; off <<= 1) {
        int y = __shfl_up_sync(0xffffffffu, x, off);
        if (lane >= off) x += y;
    }
    __shared__ int wsum[8];
    if (lane == 31) wsum[w] = x;
    __syncthreads();
    if (w == 0) {
        int s = (lane < 8) ? wsum[lane] : 0;
        #pragma unroll
        for (int off = 1; off < 8; off <<= 1) {
            int y = __shfl_up_sync(0xffffffffu, s, off);
            if (lane >= off) s += y;
        }
        if (lane < 8) wsum[lane] = s;
    }
    __syncthreads();
    int incl = x + (w > 0 ? wsum[w - 1] : 0);
    if (i < N_NODES) g_rowptr[i + 1] = incl;
    if (t == SCAN_B - 1) g_bsum[blockIdx.x] = incl;
    if (i == 0) g_rowptr[0] = 0;
}

__global__ void k_scan2() {
    int t = threadIdx.x;
    int v = (t < NSB) ? g_bsum[t] : 0;
    int lane = t & 31, w = t >> 5;
    int x = v;
    #pragma unroll
    for (int off = 1; off < 32; off <<= 1) {
        int y = __shfl_up_sync(0xffffffffu, x, off);
        if (lane >= off) x += y;
    }
    __shared__ int wsum[8];
    if (lane == 31) wsum[w] = x;
    __syncthreads();
    if (w == 0) {
        int s = (lane < 8) ? wsum[lane] : 0;
        #pragma unroll
        for (int off = 1; off < 8; off <<= 1) {
            int y = __shfl_up_sync(0xffffffffu, s, off);
            if (lane >= off) s += y;
        }
        if (lane < 8) wsum[lane] = s;
    }
    __syncthreads();
    int incl = x + (w > 0 ? wsum[w - 1] : 0);
    if (t < NSB) g_bsum[t] = incl - v;   // exclusive
}

// finalize rowptr + pos + norm; reset deg for next replay; zero col stats
__global__ void k_scan3np() {
    int t = threadIdx.x;
    if (blockIdx.x == 0) {
        if (t < IN_DIM) g_colsum[t] = 0.f;
        else if (t < 2 * IN_DIM) g_colsq[t - IN_DIM] = 0.f;
    }
    int i = blockIdx.x * SCAN_B + t;
    if (i >= N_NODES) return;
    int incl = g_rowptr[i + 1] + g_bsum[blockIdx.x];
    g_rowptr[i + 1] = incl;
    int d = g_deg[i];
    g_pos[i] = incl - d;
    g_norm[i] = rsqrtf(fmaxf((float)d, 1.0f));
    g_deg[i] = 0;
}

// ---------------- fused fill + fp16 pre-scale --------------------------------
#define NEB ((N_EDGES + 255) / 256)
__global__ void k_fill_pre(const int* __restrict__ src, const int* __restrict__ dst,
                           const float4* __restrict__ feat) {
    int b = blockIdx.x;
    if (b < NEB) {
        int i = b * 256 + threadIdx.x;
        if (i < N_EDGES) {
            int slot = atomicAdd(&g_pos[dst[i]], 1);
            g_esrc[slot] = src[i];
        }
    } else {
        int i = (b - NEB) * 256 + threadIdx.x;
        if (i < N_NODES * CH) {
            int row = i / CH;
            float n = __ldg(&g_norm[row]);
            float4 f = __ldg(&feat[i]);
            half2 a = __floats2half2_rn(f.x * n, f.y * n);
            half2 c = __floats2half2_rn(f.z * n, f.w * n);
            uint2 o;
            o.x = *(unsigned*)&a;
            o.y = *(unsigned*)&c;
            g_P[i] = o;
        }
    }
}

// ---------------- pull SpMM (fp16 gather, fp32 accumulate) — R4 proven -------
// MODE 1: P -> Q, epilogue norm^2
// MODE 2: Q -> P, epilogue norm^2
// MODE 3: P -> g_B0 fp32, epilogue norm
template <int MODE>
__global__ void k_spmm16() {
    const uint2* __restrict__ in = (MODE == 2) ? g_Q : g_P;

    int t = threadIdx.x;
    if (t >= NODES_PER_BLK * CH) return;
    int local = t / CH;
    int c = t - local * CH;
    int node = blockIdx.x * NODES_PER_BLK + local;
    if (node >= N_NODES) return;

    int beg = __ldg(&g_rowptr[node]);
    int end = __ldg(&g_rowptr[node + 1]);

    float ax = 0.f, ay = 0.f, az = 0.f, aw = 0.f;
    int e = beg;
    for (; e + 1 < end; e += 2) {
        int s0 = __ldg(&g_esrc[e]);
        int s1 = __ldg(&g_esrc[e + 1]);
        uint2 r0 = __ldg(&in[s0 * CH + c]);
        uint2 r1 = __ldg(&in[s1 * CH + c]);
        float2 a0 = __half22float2(*(half2*)&r0.x);
        float2 b0 = __half22float2(*(half2*)&r0.y);
        float2 a1 = __half22float2(*(half2*)&r1.x);
        float2 b1 = __half22float2(*(half2*)&r1.y);
        ax += a0.x + a1.x; ay += a0.y + a1.y;
        az += b0.x + b1.x; aw += b0.y + b1.y;
    }
    if (e < end) {
        int s = __ldg(&g_esrc[e]);
        uint2 r = __ldg(&in[s * CH + c]);
        float2 a = __half22float2(*(half2*)&r.x);
        float2 b = __half22float2(*(half2*)&r.y);
        ax += a.x; ay += a.y; az += b.x; aw += b.y;
    }

    float n = __ldg(&g_norm[node]);
    if (MODE == 3) {
        g_B0[node * CH + c] = make_float4(ax * n, ay * n, az * n, aw * n);
    } else {
        float f = n * n;
        half2 h0 = __floats2half2_rn(ax * f, ay * f);
        half2 h1 = __floats2half2_rn(az * f, aw * f);
        uint2 o;
        o.x = *(unsigned*)&h0;
        o.y = *(unsigned*)&h1;
        ((MODE == 1) ? g_Q : g_P)[node * CH + c] = o;
    }
}

// ---------------- column stats over final H (g_B0) — R4 proven ---------------
__global__ void k_stats(int n_slots_total) {
    __shared__ float ssum[CH][4];
    __shared__ float ssq[CH][4];
    int tid = threadIdx.x;
    if (tid < CH) {
        #pragma unroll
        for (int k = 0; k < 4; k++) { ssum[tid][k] = 0.f; ssq[tid][k] = 0.f; }
    }
    __syncthreads();

    int chunk = tid % CH;
    int slot  = tid / CH;
    float4 psum = make_float4(0, 0, 0, 0);
    float4 psq  = make_float4(0, 0, 0, 0);
    if (slot < NODES_PER_BLK) {
        int rowslot = blockIdx.x * NODES_PER_BLK + slot;
        for (int r = rowslot; r < N_NODES; r += n_slots_total) {
            float4 v = g_B0[r * CH + chunk];
            psum.x += v.x; psum.y += v.y; psum.z += v.z; psum.w += v.w;
            psq.x += v.x * v.x; psq.y += v.y * v.y; psq.z += v.z * v.z; psq.w += v.w * v.w;
        }
        atomicAdd(&ssum[chunk][0], psum.x); atomicAdd(&ssum[chunk][1], psum.y);
        atomicAdd(&ssum[chunk][2], psum.z); atomicAdd(&ssum[chunk][3], psum.w);
        atomicAdd(&ssq[chunk][0], psq.x);  atomicAdd(&ssq[chunk][1], psq.y);
        atomicAdd(&ssq[chunk][2], psq.z);  atomicAdd(&ssq[chunk][3], psq.w);
    }
    __syncthreads();
    if (tid < CH) {
        #pragma unroll
        for (int k = 0; k < 4; k++) {
            atomicAdd(&g_colsum[tid * 4 + k], ssum[tid][k]);
            atomicAdd(&g_colsq[tid * 4 + k], ssq[tid][k]);
        }
    }
}

// ---------------- fused fold + GEMM — R4 proven ------------------------------
__global__ void k_gemm_fold(const float* __restrict__ W, const float* __restrict__ b,
                            float* __restrict__ out) {
    __shared__ float s_mean[IN_DIM];
    __shared__ float s_istd[IN_DIM];
    __shared__ __align__(16) float s_Wt[IN_DIM * OUT_DIM];
    __shared__ float s_bn[OUT_DIM];
    int t = threadIdx.x;

    if (t < IN_DIM) {
        float mean = g_colsum[t] / (float)N_NODES;
        float var = (g_colsq[t] - (float)N_NODES * mean * mean) / (float)(N_NODES - 1);
        s_mean[t] = mean;
        s_istd[t] = rsqrtf(var);
    }
    __syncthreads();
    for (int i = t; i < IN_DIM * OUT_DIM; i += blockDim.x) {
        int o = i / IN_DIM;
        int f = i - o * IN_DIM;
        s_Wt[f * OUT_DIM + o] = __ldg(&W[i]) * s_istd[f];
    }
    if (t < OUT_DIM) {
        float acc = __ldg(&b[t]);
        for (int f = 0; f < IN_DIM; f++)
            acc -= s_mean[f] * s_istd[f] * __ldg(&W[t * IN_DIM + f]);
        s_bn[t] = acc;
    }
    __syncthreads();

    int row = blockIdx.x * blockDim.x + t;
    if (row >= N_NODES) return;

    float acc[OUT_DIM];
    #pragma unroll
    for (int o = 0; o < OUT_DIM; o++) acc[o] = s_bn[o];

    #pragma unroll
    for (int c = 0; c < CH; c++) {
        float4 h4 = g_B0[row * CH + c];
        #pragma unroll
        for (int k = 0; k < 4; k++) {
            float hv = (k == 0) ? h4.x : (k == 1) ? h4.y : (k == 2) ? h4.z : h4.w;
            const float4* wr = (const float4*)&s_Wt[(c * 4 + k) * OUT_DIM];
            #pragma unroll
            for (int j = 0; j < 10; j++) {
                float4 w = wr[j];
                acc[4 * j + 0] += hv * w.x;
                acc[4 * j + 1] += hv * w.y;
                acc[4 * j + 2] += hv * w.z;
                acc[4 * j + 3] += hv * w.w;
            }
        }
    }
    float4* op = (float4*)(out + (size_t)row * OUT_DIM);
    #pragma unroll
    for (int j = 0; j < 10; j++)
        op[j] = make_float4(acc[4 * j + 0], acc[4 * j + 1], acc[4 * j + 2], acc[4 * j + 3]);
}

// ---------------- launch ------------------------------------------------------

extern "C" void kernel_launch(void* const* d_in, const int* in_sizes, int n_in,
                              void* d_out, int out_size) {
    const float4* feat = (const float4*)d_in[0];   // [N, 100] f32
    const float*  W    = (const float*)d_in[1];    // [40, 100] f32
    const float*  b    = (const float*)d_in[2];    // [40] f32
    const int*    src  = (const int*)d_in[3];      // [E] i32
    const int*    dst  = (const int*)d_in[4];      // [E] i32
    float*        out  = (float*)d_out;            // [N, 40] f32

    const int TB = 256;
    const int n_node_blk  = (N_NODES + TB - 1) / TB;
    const int n_edge_blk  = (N_EDGES + TB - 1) / TB;
    const int n_chunk_blk = (N_NODES * CH + TB - 1) / TB;
    const int n_spmm_blk  = (N_NODES + NODES_PER_BLK - 1) / NODES_PER_BLK;

    k_degree<<<n_edge_blk, TB>>>(dst);
    k_scan1<<<NSB, SCAN_B>>>();
    k_scan2<<<1, SCAN_B>>>();
    k_scan3np<<<NSB, SCAN_B>>>();
    k_fill_pre<<<n_edge_blk + n_chunk_blk, TB>>>(src, dst, feat);

    k_spmm16<1><<<n_spmm_blk, TB>>>();   // P -> Q
    k_spmm16<2><<<n_spmm_blk, TB>>>();   // Q -> P
    k_spmm16<3><<<n_spmm_blk, TB>>>();   // P -> B0 (fp32)

    const int STAT_BLKS = 128;
    k_stats<<<STAT_BLKS, TB>>>(STAT_BLKS * NODES_PER_BLK);
    k_gemm_fold<<<n_node_blk, TB>>>(W, b, out);
}

// round 8
// speedup vs baseline: 1.2617x; 1.0486x over previous
#include <cuda_runtime.h>
#include <cuda_fp16.h>

#define N_NODES 50000
#define N_EDGES 800000
#define IN_DIM  100
#define OUT_DIM 40
#define CH      25           // float4 chunks per fp32 row (100/4)
#define LW      32           // fp16 row = 32 uint2 lanes = 256B (100 used + pad)
#define SCAN_B  256
#define NSB     196          // ceil(50000/256)
#define NODES_PER_BLK 10     // for stats kernel
#define WPB     8            // warps (nodes) per spmm block

// ---------------- scratch (device globals) ----------------------------------
__device__ float4 g_B0[N_NODES * CH];                     // final H (fp32)
__device__ __align__(256) uint2 g_P[N_NODES * LW];        // fp16 ping, 256B rows
__device__ __align__(256) uint2 g_Q[N_NODES * LW];        // fp16 pong
__device__ float  g_norm[N_NODES];
__device__ int    g_deg[N_NODES];
__device__ int    g_rowptr[N_NODES + 1];
__device__ int    g_pos[N_NODES];
__device__ int    g_bsum[NSB];
__device__ int    g_esrc[N_EDGES];
__device__ float  g_colsum[IN_DIM];
__device__ float  g_colsq[IN_DIM];

// ---------------- degree histogram (g_deg zeroed by prev run / BSS init) -----
__global__ void k_degree(const int* __restrict__ dst) {
    int i = blockIdx.x * blockDim.x + threadIdx.x;
    if (i < N_EDGES) atomicAdd(&g_deg[dst[i]], 1);
}

// ---- warp-shuffle scan chain ----
__global__ void k_scan1() {
    int t = threadIdx.x;
    int i = blockIdx.x * SCAN_B + t;
    int v = (i < N_NODES) ? g_deg[i] : 0;
    int lane = t & 31, w = t >> 5;
    int x = v;
    #pragma unroll
    for (int off = 1; off < 32; off <<= 1) {
        int y = __shfl_up_sync(0xffffffffu, x, off);
        if (lane >= off) x += y;
    }
    __shared__ int wsum[8];
    if (lane == 31) wsum[w] = x;
    __syncthreads();
    if (w == 0) {
        int s = (lane < 8) ? wsum[lane] : 0;
        #pragma unroll
        for (int off = 1; off < 8; off <<= 1) {
            int y = __shfl_up_sync(0xffffffffu, s, off);
            if (lane >= off) s += y;
        }
        if (lane < 8) wsum[lane] = s;
    }
    __syncthreads();
    int incl = x + (w > 0 ? wsum[w - 1] : 0);
    if (i < N_NODES) g_rowptr[i + 1] = incl;
    if (t == SCAN_B - 1) g_bsum[blockIdx.x] = incl;
    if (i == 0) g_rowptr[0] = 0;
}

__global__ void k_scan2() {
    int t = threadIdx.x;
    int v = (t < NSB) ? g_bsum[t] : 0;
    int lane = t & 31, w = t >> 5;
    int x = v;
    #pragma unroll
    for (int off = 1; off < 32; off <<= 1) {
        int y = __shfl_up_sync(0xffffffffu, x, off);
        if (lane >= off) x += y;
    }
    __shared__ int wsum[8];
    if (lane == 31) wsum[w] = x;
    __syncthreads();
    if (w == 0) {
        int s = (lane < 8) ? wsum[lane] : 0;
        #pragma unroll
        for (int off = 1; off < 8; off <<= 1) {
            int y = __shfl_up_sync(0xffffffffu, s, off);
            if (lane >= off) s += y;
        }
        if (lane < 8) wsum[lane] = s;
    }
    __syncthreads();
    int incl = x + (w > 0 ? wsum[w - 1] : 0);
    if (t < NSB) g_bsum[t] = incl - v;   // exclusive
}

// finalize rowptr + pos + norm; reset deg; zero col stats
__global__ void k_scan3np() {
    int t = threadIdx.x;
    if (blockIdx.x == 0) {
        if (t < IN_DIM) g_colsum[t] = 0.f;
        else if (t < 2 * IN_DIM) g_colsq[t - IN_DIM] = 0.f;
    }
    int i = blockIdx.x * SCAN_B + t;
    if (i >= N_NODES) return;
    int incl = g_rowptr[i + 1] + g_bsum[blockIdx.x];
    g_rowptr[i + 1] = incl;
    int d = g_deg[i];
    g_pos[i] = incl - d;
    g_norm[i] = rsqrtf(fmaxf((float)d, 1.0f));
    g_deg[i] = 0;
}

// ---------------- fused fill + fp16 pre-scale (padded 256B rows) -------------
#define NEB ((N_EDGES + 255) / 256)
__global__ void k_fill_pre(const int* __restrict__ src, const int* __restrict__ dst,
                           const float4* __restrict__ feat) {
    int b = blockIdx.x;
    if (b < NEB) {
        int i = b * 256 + threadIdx.x;
        if (i < N_EDGES) {
            int slot = atomicAdd(&g_pos[dst[i]], 1);
            g_esrc[slot] = src[i];
        }
    } else {
        int i = (b - NEB) * 256 + threadIdx.x;
        if (i < N_NODES * LW) {
            int row = i >> 5;
            int lane = i & 31;
            uint2 o = make_uint2(0u, 0u);
            if (lane < CH) {
                float n = __ldg(&g_norm[row]);
                float4 f = __ldg(&feat[row * CH + lane]);
                half2 a = __floats2half2_rn(f.x * n, f.y * n);
                half2 c = __floats2half2_rn(f.z * n, f.w * n);
                o.x = *(unsigned*)&a;
                o.y = *(unsigned*)&c;
            }
            g_P[i] = o;
        }
    }
}

// ---------------- pull SpMM: warp-per-node, shfl-broadcast indices -----------
// MODE 1: P -> Q, epilogue norm^2
// MODE 2: Q -> P, epilogue norm^2
// MODE 3: P -> g_B0 fp32, epilogue norm (lanes < 25 only)
template <int MODE>
__global__ void __launch_bounds__(WPB * 32) k_spmm16() {
    const uint2* __restrict__ in = (MODE == 2) ? g_Q : g_P;

    int t = threadIdx.x;
    int w = t >> 5;
    int lane = t & 31;
    int node = blockIdx.x * WPB + w;          // 50000 = 6250 * 8 exactly

    int beg = __ldg(&g_rowptr[node]);
    int end = __ldg(&g_rowptr[node + 1]);

    float ax = 0.f, ay = 0.f, az = 0.f, aw = 0.f;

    for (int base = beg; base < end; base += 32) {
        int rem = end - base;
        int idx = (lane < rem) ? __ldg(&g_esrc[base + lane]) : 0;
        int cnt = (rem < 32) ? rem : 32;
        int j = 0;
        for (; j + 3 < cnt; j += 4) {
            int s0 = __shfl_sync(0xffffffffu, idx, j);
            int s1 = __shfl_sync(0xffffffffu, idx, j + 1);
            int s2 = __shfl_sync(0xffffffffu, idx, j + 2);
            int s3 = __shfl_sync(0xffffffffu, idx, j + 3);
            uint2 r0 = __ldg(&in[s0 * LW + lane]);
            uint2 r1 = __ldg(&in[s1 * LW + lane]);
            uint2 r2 = __ldg(&in[s2 * LW + lane]);
            uint2 r3 = __ldg(&in[s3 * LW + lane]);
            float2 p0 = __half22float2(*(half2*)&r0.x), q0 = __half22float2(*(half2*)&r0.y);
            float2 p1 = __half22float2(*(half2*)&r1.x), q1 = __half22float2(*(half2*)&r1.y);
            float2 p2 = __half22float2(*(half2*)&r2.x), q2 = __half22float2(*(half2*)&r2.y);
            float2 p3 = __half22float2(*(half2*)&r3.x), q3 = __half22float2(*(half2*)&r3.y);
            ax += (p0.x + p1.x) + (p2.x + p3.x);
            ay += (p0.y + p1.y) + (p2.y + p3.y);
            az += (q0.x + q1.x) + (q2.x + q3.x);
            aw += (q0.y + q1.y) + (q2.y + q3.y);
        }
        for (; j < cnt; j++) {
            int s = __shfl_sync(0xffffffffu, idx, j);
            uint2 r = __ldg(&in[s * LW + lane]);
            float2 p = __half22float2(*(half2*)&r.x);
            float2 q = __half22float2(*(half2*)&r.y);
            ax += p.x; ay += p.y; az += q.x; aw += q.y;
        }
    }

    float n = __ldg(&g_norm[node]);
    if (MODE == 3) {
        if (lane < CH)
            g_B0[node * CH + lane] = make_float4(ax * n, ay * n, az * n, aw * n);
    } else {
        float f = n * n;
        half2 h0 = __floats2half2_rn(ax * f, ay * f);
        half2 h1 = __floats2half2_rn(az * f, aw * f);
        uint2 o;
        o.x = *(unsigned*)&h0;
        o.y = *(unsigned*)&h1;
        ((MODE == 1) ? g_Q : g_P)[node * LW + lane] = o;   // pad lanes rewrite 0
    }
}

// ---------------- column stats over final H (g_B0) ---------------------------
__global__ void k_stats(int n_slots_total) {
    __shared__ float ssum[CH][4];
    __shared__ float ssq[CH][4];
    int tid = threadIdx.x;
    if (tid < CH) {
        #pragma unroll
        for (int k = 0; k < 4; k++) { ssum[tid][k] = 0.f; ssq[tid][k] = 0.f; }
    }
    __syncthreads();

    int chunk = tid % CH;
    int slot  = tid / CH;
    float4 psum = make_float4(0, 0, 0, 0);
    float4 psq  = make_float4(0, 0, 0, 0);
    if (slot < NODES_PER_BLK) {
        int rowslot = blockIdx.x * NODES_PER_BLK + slot;
        for (int r = rowslot; r < N_NODES; r += n_slots_total) {
            float4 v = g_B0[r * CH + chunk];
            psum.x += v.x; psum.y += v.y; psum.z += v.z; psum.w += v.w;
            psq.x += v.x * v.x; psq.y += v.y * v.y; psq.z += v.z * v.z; psq.w += v.w * v.w;
        }
        atomicAdd(&ssum[chunk][0], psum.x); atomicAdd(&ssum[chunk][1], psum.y);
        atomicAdd(&ssum[chunk][2], psum.z); atomicAdd(&ssum[chunk][3], psum.w);
        atomicAdd(&ssq[chunk][0], psq.x);  atomicAdd(&ssq[chunk][1], psq.y);
        atomicAdd(&ssq[chunk][2], psq.z);  atomicAdd(&ssq[chunk][3], psq.w);
    }
    __syncthreads();
    if (tid < CH) {
        #pragma unroll
        for (int k = 0; k < 4; k++) {
            atomicAdd(&g_colsum[tid * 4 + k], ssum[tid][k]);
            atomicAdd(&g_colsq[tid * 4 + k], ssq[tid][k]);
        }
    }
}

// ---------------- fused fold + GEMM ------------------------------------------
__global__ void k_gemm_fold(const float* __restrict__ W, const float* __restrict__ b,
                            float* __restrict__ out) {
    __shared__ float s_mean[IN_DIM];
    __shared__ float s_istd[IN_DIM];
    __shared__ __align__(16) float s_Wt[IN_DIM * OUT_DIM];
    __shared__ float s_bn[OUT_DIM];
    int t = threadIdx.x;

    if (t < IN_DIM) {
        float mean = g_colsum[t] / (float)N_NODES;
        float var = (g_colsq[t] - (float)N_NODES * mean * mean) / (float)(N_NODES - 1);
        s_mean[t] = mean;
        s_istd[t] = rsqrtf(var);
    }
    __syncthreads();
    for (int i = t; i < IN_DIM * OUT_DIM; i += blockDim.x) {
        int o = i / IN_DIM;
        int f = i - o * IN_DIM;
        s_Wt[f * OUT_DIM + o] = __ldg(&W[i]) * s_istd[f];
    }
    if (t < OUT_DIM) {
        float acc = __ldg(&b[t]);
        for (int f = 0; f < IN_DIM; f++)
            acc -= s_mean[f] * s_istd[f] * __ldg(&W[t * IN_DIM + f]);
        s_bn[t] = acc;
    }
    __syncthreads();

    int row = blockIdx.x * blockDim.x + t;
    if (row >= N_NODES) return;

    float acc[OUT_DIM];
    #pragma unroll
    for (int o = 0; o < OUT_DIM; o++) acc[o] = s_bn[o];

    #pragma unroll
    for (int c = 0; c < CH; c++) {
        float4 h4 = g_B0[row * CH + c];
        #pragma unroll
        for (int k = 0; k < 4; k++) {
            float hv = (k == 0) ? h4.x : (k == 1) ? h4.y : (k == 2) ? h4.z : h4.w;
            const float4* wr = (const float4*)&s_Wt[(c * 4 + k) * OUT_DIM];
            #pragma unroll
            for (int j = 0; j < 10; j++) {
                float4 w = wr[j];
                acc[4 * j + 0] += hv * w.x;
                acc[4 * j + 1] += hv * w.y;
                acc[4 * j + 2] += hv * w.z;
                acc[4 * j + 3] += hv * w.w;
            }
        }
    }
    float4* op = (float4*)(out + (size_t)row * OUT_DIM);
    #pragma unroll
    for (int j = 0; j < 10; j++)
        op[j] = make_float4(acc[4 * j + 0], acc[4 * j + 1], acc[4 * j + 2], acc[4 * j + 3]);
}

// ---------------- launch ------------------------------------------------------

extern "C" void kernel_launch(void* const* d_in, const int* in_sizes, int n_in,
                              void* d_out, int out_size) {
    const float4* feat = (const float4*)d_in[0];   // [N, 100] f32
    const float*  W    = (const float*)d_in[1];    // [40, 100] f32
    const float*  b    = (const float*)d_in[2];    // [40] f32
    const int*    src  = (const int*)d_in[3];      // [E] i32
    const int*    dst  = (const int*)d_in[4];      // [E] i32
    float*        out  = (float*)d_out;            // [N, 40] f32

    const int TB = 256;
    const int n_node_blk  = (N_NODES + TB - 1) / TB;
    const int n_edge_blk  = (N_EDGES + TB - 1) / TB;
    const int n_pad_blk   = (N_NODES * LW + TB - 1) / TB;
    const int n_spmm_blk  = N_NODES / WPB;        // 6250, exact

    k_degree<<<n_edge_blk, TB>>>(dst);
    k_scan1<<<NSB, SCAN_B>>>();
    k_scan2<<<1, SCAN_B>>>();
    k_scan3np<<<NSB, SCAN_B>>>();
    k_fill_pre<<<n_edge_blk + n_pad_blk, TB>>>(src, dst, feat);

    k_spmm16<1><<<n_spmm_blk, TB>>>();   // P -> Q
    k_spmm16<2><<<n_spmm_blk, TB>>>();   // Q -> P
    k_spmm16<3><<<n_spmm_blk, TB>>>();   // P -> B0 (fp32)

    const int STAT_BLKS = 128;
    k_stats<<<STAT_BLKS, TB>>>(STAT_BLKS * NODES_PER_BLK);
    k_gemm_fold<<<n_node_blk, TB>>>(W, b, out);
}